// round 10
// baseline (speedup 1.0000x reference)
#include <cuda_runtime.h>
#include <cuda_fp16.h>

#define B_ 2
#define L_ 24
#define C_ 16
#define H_ 64
#define W_ 64
#define HW_ 4096

// fp16 images, layout [b][l][cq(2)][HW][8ch] : 16 B per (pixel, channel-oct)
__device__ __half g_imgh[(size_t)B_ * L_ * 2 * HW_ * 8];

// ---------------------------------------------------------------------------
// Kernel 1: repack [B][L][C][HW] fp32 -> [b][l][cq][HW][8] fp16.
// ---------------------------------------------------------------------------
__global__ __launch_bounds__(256) void transpose_kernel(const float* __restrict__ images) {
    int idx = blockIdx.x * blockDim.x + threadIdx.x;   // over B*L*2*HW
    int p = idx & (HW_ - 1);
    int cq = (idx >> 12) & 1;
    int bl = idx >> 13;
    const float* src = images + ((size_t)bl * C_ + cq * 8) * HW_ + p;
    __half2 h[4];
#pragma unroll
    for (int j = 0; j < 4; ++j)
        h[j] = __floats2half2_rn(src[(2 * j) * HW_], src[(2 * j + 1) * HW_]);
    ((uint4*)g_imgh)[idx] = *(uint4*)h;
}

// ---------------------------------------------------------------------------
// Accumulate 8 fp16 channels (one uint4) * weight into fp32 acc.
// ---------------------------------------------------------------------------
__device__ __forceinline__ void accum8(float* acc, uint4 a, float w) {
    unsigned wds[4] = {a.x, a.y, a.z, a.w};
#pragma unroll
    for (int j = 0; j < 4; ++j) {
        float2 f = __half22float2(*(__half2*)&wds[j]);
        acc[2 * j]     = fmaf(w, f.x, acc[2 * j]);
        acc[2 * j + 1] = fmaf(w, f.y, acc[2 * j + 1]);
    }
}

// ---------------------------------------------------------------------------
// One t-phase: thread accumulates 8 channels (its cq) over k = t..0, writes out.
// ---------------------------------------------------------------------------
__device__ __forceinline__ void do_target(int b, int t, int cq, int p,
                                          float ax, float yf,
                                          const float* __restrict__ flows,
                                          float* __restrict__ out) {
    const float* fptr = flows + ((size_t)(b * L_ + t) * 2) * HW_ + p;
    const __half* ibase = g_imgh + ((size_t)(b * L_ + t) * 2 + cq) * HW_ * 8;

    float relx = 0.0f, rely = 0.0f;
    float acc[8];
#pragma unroll
    for (int c = 0; c < 8; ++c) acc[c] = 0.0f;

    for (int k = t; k >= 0; --k) {
        float fx = 0.0f, fy = 0.0f;
        if (k > 0) { fx = fptr[0]; fy = fptr[HW_]; }   // prefetch flow_k

        // wrap x: u = (gx+1) mod 2, ix = u*32 - 0.5 in [-0.5, 63.5)
        float u0 = ax + relx;
        float u = u0 - 2.0f * floorf(0.5f * u0);
        float ixf = fmaf(u, 32.0f, -0.5f);
        float iyf = fmaf(rely, 32.0f, yf);

        float x0f = floorf(ixf), y0f = floorf(iyf);
        float wx1 = ixf - x0f, wy1 = iyf - y0f;
        float wx0 = 1.0f - wx1, wy0 = 1.0f - wy1;
        int x0 = (int)x0f, y0 = (int)y0f;

        // validity folded into weights (x wrapped => x0 in [-1,63])
        if (x0 < 0) wx0 = 0.0f;
        if (x0 > 62) wx1 = 0.0f;
        if ((unsigned)y0 > 63u) wy0 = 0.0f;
        if ((unsigned)(y0 + 1) > 63u) wy1 = 0.0f;

        float w00 = wx0 * wy0, w10 = wx1 * wy0;
        float w01 = wx0 * wy1, w11 = wx1 * wy1;

        int x0c = max(x0, 0), x1c = min(x0 + 1, 63);
        int y0c = min(max(y0, 0), 63), y1c = min(max(y0 + 1, 0), 63);

        const uint4* src = (const uint4*)ibase;
        // batch the 4 corner loads for MLP
        uint4 a00 = src[(y0c << 6) + x0c];
        uint4 a10 = src[(y0c << 6) + x1c];
        uint4 a01 = src[(y1c << 6) + x0c];
        uint4 a11 = src[(y1c << 6) + x1c];

        accum8(acc, a00, w00); accum8(acc, a10, w10);
        accum8(acc, a01, w01); accum8(acc, a11, w11);

        relx += fx;
        rely += fy;
        fptr -= 2 * HW_;
        ibase -= (size_t)2 * HW_ * 8;
    }

    // out layout [B][L][C][H][W]; warp writes 128B coalesced per channel
    float* op = out + ((size_t)(b * L_ + t) * C_ + cq * 8) * HW_ + p;
#pragma unroll
    for (int c = 0; c < 8; ++c) op[c * HW_] = acc[c];
}

// ---------------------------------------------------------------------------
// Kernel 2: main gather. Block = 128 threads = 1 row x 2 channel-octs
// (warps 0-1: cq0 for 64 px, warps 2-3: cq1). Grid (64, 12, 2); block i
// handles t1 = 23-i and t2 = i => uniform 25 k-iterations per block.
// 197K resident threads -> occ ~60%.
// ---------------------------------------------------------------------------
__global__ __launch_bounds__(128) void warp_kernel(const float* __restrict__ flows,
                                                   float* __restrict__ out) {
    int tid = threadIdx.x;
    int x = tid & 63;               // pixel in row
    int cq = tid >> 6;              // channel oct (warp-aligned)
    int y = blockIdx.x;
    int i = blockIdx.y;             // 0..11
    int b = blockIdx.z;
    int p = (y << 6) + x;

    float ax = (float)(2 * x + 1) * (1.0f / 64.0f);  // (bx + 1), pre-wrap
    float yf = (float)y;                              // iy = rely*32 + y

    do_target(b, (L_ - 1) - i, cq, p, ax, yf, flows, out);
    do_target(b, i,            cq, p, ax, yf, flows, out);
}

extern "C" void kernel_launch(void* const* d_in, const int* in_sizes, int n_in,
                              void* d_out, int out_size) {
    const float* flows = (const float*)d_in[0];
    const float* images = (const float*)d_in[1];
    float* out = (float*)d_out;

    transpose_kernel<<<(B_ * L_ * 2 * HW_) / 256, 256>>>(images);
    dim3 grid(64, 12, B_);
    warp_kernel<<<grid, 128>>>(flows, out);
}